// round 12
// baseline (speedup 1.0000x reference)
#include <cuda_runtime.h>
#include <cstdint>
#include <math.h>

#define NNODES 768
#define KNB    21
typedef unsigned long long ull;

// ---------- f32x2 PTX helpers ----------
#define FMA2(d, a, b, c) \
    asm("fma.rn.f32x2 %0, %1, %2, %3;" : "=l"(d) : "l"(a), "l"(b), "l"(c))
#define ADD2(d, a, b) \
    asm("add.rn.f32x2 %0, %1, %2;" : "=l"(d) : "l"(a), "l"(b))
#define PACK_DUP(d, s) \
    asm("mov.b64 %0, {%1, %1};" : "=l"(d) : "f"(s))
#define UNPACK2(lo, hi, v) \
    asm("mov.b64 {%0, %1}, %2;" : "=f"(lo), "=f"(hi) : "l"(v))

// packed relu: zero each 32-bit half whose sign bit is set (ALU-pipe ops)
__device__ __forceinline__ ull relu2(ull s) {
    ull sgn = (s >> 31) & 0x0000000100000001ull;
    ull msk = sgn * 0xFFFFFFFFull;
    return s & ~msk;
}

// ---------------- scratch ----------------
__device__ float g_fafbA[NNODES * 512];
__device__ float g_fafbB[NNODES * 512];
__device__ float g_xpA[NNODES * 1024];
__device__ float g_xpB[NNODES * 1024];
__device__ float g_xp[NNODES * 1024];
__device__ float g_rel[NNODES * NNODES];
__device__ int   g_nbr[NNODES * KNB];
__device__ float g_asrc[NNODES * 4];
__device__ float g_adst[NNODES * 4];
__device__ float g_h1[NNODES * 1024];
__device__ float g_hidP[16 * NNODES * 128];
__device__ float g_x2[NNODES * 2];
__device__ float g_a2s[NNODES];
__device__ float g_a2d[NNODES];

// =========== shared 128x128 FFMA2 GEMM core (reg-prefetch double buffer) ===========
template<bool GEOM_TAIL>
__device__ __forceinline__ void gemm128(const float* __restrict__ Abase, int lda,
                                        const float* __restrict__ Bbase, int ldb,
                                        float* __restrict__ Cbase, int ldc,
                                        int k0, int k1,
                                        const float* __restrict__ Wtail,
                                        const float* __restrict__ boxes, int row0) {
    __shared__ float As[16][132];
    __shared__ float Bs[16][132];
    __shared__ float Wt[4][128];

    const int tid = threadIdx.x;
    if (GEOM_TAIL && tid < 128) {
        int d = tid >> 5, c4 = (tid & 31) * 4;
        *(float4*)&Wt[d][c4] = *(const float4*)(Wtail + d * ldb + c4);
    }

    const int arow = tid >> 1, ak8 = (tid & 1) * 8;
    const int brow = tid >> 4, bc8 = (tid & 15) * 8;
    const int ty = tid >> 4, tx = tid & 15;

    ull acc[8][4];
    #pragma unroll
    for (int i = 0; i < 8; i++)
        #pragma unroll
        for (int j = 0; j < 4; j++) acc[i][j] = 0ull;

    float4 a0 = *(const float4*)(Abase + arow * lda + k0 + ak8);
    float4 a1 = *(const float4*)(Abase + arow * lda + k0 + ak8 + 4);
    float4 b0 = *(const float4*)(Bbase + (k0 + brow) * ldb + bc8);
    float4 b1 = *(const float4*)(Bbase + (k0 + brow) * ldb + bc8 + 4);

    for (int k = k0; k < k1; k += 16) {
        __syncthreads();
        As[ak8 + 0][arow] = a0.x; As[ak8 + 1][arow] = a0.y;
        As[ak8 + 2][arow] = a0.z; As[ak8 + 3][arow] = a0.w;
        As[ak8 + 4][arow] = a1.x; As[ak8 + 5][arow] = a1.y;
        As[ak8 + 6][arow] = a1.z; As[ak8 + 7][arow] = a1.w;
        *(float4*)&Bs[brow][bc8]     = b0;
        *(float4*)&Bs[brow][bc8 + 4] = b1;
        __syncthreads();
        if (k + 16 < k1) {
            a0 = *(const float4*)(Abase + arow * lda + k + 16 + ak8);
            a1 = *(const float4*)(Abase + arow * lda + k + 16 + ak8 + 4);
            b0 = *(const float4*)(Bbase + (k + 16 + brow) * ldb + bc8);
            b1 = *(const float4*)(Bbase + (k + 16 + brow) * ldb + bc8 + 4);
        }
        #pragma unroll
        for (int kk = 0; kk < 16; kk++) {
            float4 af0 = *(const float4*)&As[kk][ty * 8];
            float4 af1 = *(const float4*)&As[kk][ty * 8 + 4];
            float4 bf0 = *(const float4*)&Bs[kk][tx * 8];
            float4 bf1 = *(const float4*)&Bs[kk][tx * 8 + 4];
            ull a2[8], b2[4];
            PACK_DUP(a2[0], af0.x); PACK_DUP(a2[1], af0.y);
            PACK_DUP(a2[2], af0.z); PACK_DUP(a2[3], af0.w);
            PACK_DUP(a2[4], af1.x); PACK_DUP(a2[5], af1.y);
            PACK_DUP(a2[6], af1.z); PACK_DUP(a2[7], af1.w);
            b2[0] = ((const ull*)&bf0)[0]; b2[1] = ((const ull*)&bf0)[1];
            b2[2] = ((const ull*)&bf1)[0]; b2[3] = ((const ull*)&bf1)[1];
            #pragma unroll
            for (int i = 0; i < 8; i++) {
                FMA2(acc[i][0], a2[i], b2[0], acc[i][0]);
                FMA2(acc[i][1], a2[i], b2[1], acc[i][1]);
                FMA2(acc[i][2], a2[i], b2[2], acc[i][2]);
                FMA2(acc[i][3], a2[i], b2[3], acc[i][3]);
            }
        }
    }

    if (GEOM_TAIL) {
        __syncthreads();
        const float inv800 = 1.0f / 800.0f;
        #pragma unroll
        for (int i = 0; i < 8; i++) {
            int row = row0 + ty * 8 + i;
            float4 bx4 = *(const float4*)(boxes + row * 4);
            ull g2[4];
            PACK_DUP(g2[0], bx4.x * inv800); PACK_DUP(g2[1], bx4.y * inv800);
            PACK_DUP(g2[2], bx4.z * inv800); PACK_DUP(g2[3], bx4.w * inv800);
            #pragma unroll
            for (int d = 0; d < 4; d++) {
                const ull* wrow = (const ull*)&Wt[d][tx * 8];
                FMA2(acc[i][0], g2[d], wrow[0], acc[i][0]);
                FMA2(acc[i][1], g2[d], wrow[1], acc[i][1]);
                FMA2(acc[i][2], g2[d], wrow[2], acc[i][2]);
                FMA2(acc[i][3], g2[d], wrow[3], acc[i][3]);
            }
        }
    }

    #pragma unroll
    for (int i = 0; i < 8; i++) {
        float* crow = Cbase + (ty * 8 + i) * ldc + tx * 8;
        ulonglong2 o0; o0.x = acc[i][0]; o0.y = acc[i][1];
        ulonglong2 o1; o1.x = acc[i][2]; o1.y = acc[i][3];
        *(ulonglong2*)(crow)     = o0;
        *(ulonglong2*)(crow + 4) = o1;
    }
}

// =========== L1: fafb (48 blocks) + xp (96 blocks) ===========
__global__ __launch_bounds__(256) void gemm_main(const float* __restrict__ feats,
                                                 const float* __restrict__ W1,
                                                 const float* __restrict__ g1W,
                                                 const float* __restrict__ boxes) {
    const int blk = blockIdx.x;
    if (blk < 48) {
        int half = blk >= 24;
        int t = blk - half * 24;
        int bx = t & 3, by = t >> 2;
        int row0 = by * 128, col0 = bx * 128;
        const float* Bb = (col0 >= 256) ? (W1 + 1024 * 256 + (col0 - 256)) : (W1 + col0);
        gemm128<false>(feats + row0 * 1024, 1024, Bb, 256,
                       (half ? g_fafbB : g_fafbA) + row0 * 512 + col0, 512,
                       half * 512, half * 512 + 512, nullptr, nullptr, 0);
    } else {
        int t = blk - 48;
        int half = t >= 48;
        int tt = t - half * 48;
        int bx = tt & 7, by = tt >> 3;
        int row0 = by * 128, col0 = bx * 128;
        if (half)
            gemm128<true>(feats + row0 * 1024, 1024, g1W + col0, 1024,
                          g_xpB + row0 * 1024 + col0, 1024,
                          512, 1024, g1W + 1024 * 1024 + col0, boxes, row0);
        else
            gemm128<false>(feats + row0 * 1024, 1024, g1W + col0, 1024,
                           g_xpA + row0 * 1024 + col0, 1024,
                           0, 512, nullptr, nullptr, 0);
    }
}

// ---------------- rel body (packed relu + packed w2 accumulate) ----------------
__device__ __forceinline__ void rel_body(int blk,
                                         const float* __restrict__ boxes,
                                         const float* __restrict__ W1,
                                         const float* __restrict__ b1,
                                         const float* __restrict__ W2,
                                         const float* __restrict__ b2,
                                         float* __restrict__ rel) {
    __shared__ float  fa_s[32][128];
    __shared__ float  fb_s[32 * 130];
    __shared__ float2 wg2_s[4][64];
    __shared__ __align__(8) float w2_s[128];
    __shared__ float  bb_s[256];

    const int i0 = (blk / 24) * 32, j0 = (blk % 24) * 32;
    const int tid = threadIdx.x;
    const int tx = tid & 31, ty = tid >> 5;

    if (tid < 128) { bb_s[tid] = boxes[i0 * 4 + tid]; bb_s[128 + tid] = boxes[j0 * 4 + tid]; }
    __syncthreads();

    float bj0 = bb_s[128 + tx * 4 + 0], bj1 = bb_s[128 + tx * 4 + 1];
    float bj2 = bb_s[128 + tx * 4 + 2], bj3 = bb_s[128 + tx * 4 + 3];
    ull d2[4][4];
    #pragma unroll
    for (int r = 0; r < 4; r++) {
        int ii = ty * 4 + r;
        float d0 = fabsf(bb_s[ii * 4 + 0] - bj0);
        float d1 = fabsf(bb_s[ii * 4 + 1] - bj1);
        float d3 = fabsf(bb_s[ii * 4 + 2] - bj2);
        float d4 = fabsf(bb_s[ii * 4 + 3] - bj3);
        PACK_DUP(d2[r][0], d0); PACK_DUP(d2[r][1], d1);
        PACK_DUP(d2[r][2], d3); PACK_DUP(d2[r][3], d4);
    }

    ull acc2[4] = {0ull, 0ull, 0ull, 0ull};
    for (int c0 = 0; c0 < 256; c0 += 128) {
        __syncthreads();
        for (int t = tid; t < 1024; t += 256) {
            int r = t >> 5, h4 = (t & 31) * 4;
            float4 vA = *(const float4*)&g_fafbA[(i0 + r) * 512 + c0 + h4];
            float4 vB = *(const float4*)&g_fafbB[(i0 + r) * 512 + c0 + h4];
            float4 bb = *(const float4*)&b1[c0 + h4];
            *(float4*)&fa_s[r][h4] = make_float4(vA.x + vB.x + bb.x, vA.y + vB.y + bb.y,
                                                 vA.z + vB.z + bb.z, vA.w + vB.w + bb.w);
            float4 wA = *(const float4*)&g_fafbA[(j0 + r) * 512 + 256 + c0 + h4];
            float4 wB = *(const float4*)&g_fafbB[(j0 + r) * 512 + 256 + c0 + h4];
            *(float2*)&fb_s[r * 130 + h4]     = make_float2(wA.x + wB.x, wA.y + wB.y);
            *(float2*)&fb_s[r * 130 + h4 + 2] = make_float2(wA.z + wB.z, wA.w + wB.w);
        }
        {
            int comp = tid >> 6, m = tid & 63;
            const float* wrow = W1 + (2048 + comp) * 256 + c0;
            wg2_s[comp][m] = make_float2(wrow[2 * m], wrow[2 * m + 1]);
        }
        if (tid < 128) w2_s[tid] = W2[c0 + tid];
        __syncthreads();
        #pragma unroll 2
        for (int m = 0; m < 64; m++) {
            ull fb2 = *(const ull*)&fb_s[tx * 130 + 2 * m];
            ull wgx = *(const ull*)&wg2_s[0][m];
            ull wgy = *(const ull*)&wg2_s[1][m];
            ull wgz = *(const ull*)&wg2_s[2][m];
            ull wgw = *(const ull*)&wg2_s[3][m];
            ull w2p = *(const ull*)&w2_s[2 * m];
            #pragma unroll
            for (int r = 0; r < 4; r++) {
                ull fa2 = *(const ull*)&fa_s[ty * 4 + r][2 * m];
                ull s;
                ADD2(s, fa2, fb2);
                FMA2(s, d2[r][0], wgx, s);
                FMA2(s, d2[r][1], wgy, s);
                FMA2(s, d2[r][2], wgz, s);
                FMA2(s, d2[r][3], wgw, s);
                s = relu2(s);
                FMA2(acc2[r], s, w2p, acc2[r]);
            }
        }
    }
    float b2v = b2[0];
    #pragma unroll
    for (int r = 0; r < 4; r++) {
        float lo, hi;
        UNPACK2(lo, hi, acc2[r]);
        int i = i0 + ty * 4 + r, j = j0 + tx;
        float v = lo + hi + b2v;
        if (i == j) v = -1e9f;
        rel[i * NNODES + j] = v;
    }
}

// ---------------- L2: rel (576) + attn coef (384) + xp sum (192) ----------------
__global__ __launch_bounds__(256) void rel_attn_kernel(const float* __restrict__ boxes,
                                                       const float* __restrict__ W1,
                                                       const float* __restrict__ b1,
                                                       const float* __restrict__ W2,
                                                       const float* __restrict__ b2,
                                                       const float* __restrict__ g1as,
                                                       const float* __restrict__ g1ad,
                                                       float* __restrict__ rel) {
    const int tid = threadIdx.x;
    if (blockIdx.x < 576) {
        rel_body(blockIdx.x, boxes, W1, b1, W2, b2, rel);
    } else if (blockIdx.x < 960) {
        const int n = (blockIdx.x - 576) * 2 + (tid >> 7);
        const int wtid = tid & 127;
        const int h = wtid >> 5, lane = tid & 31;
        float s = 0.f, ds = 0.f;
        #pragma unroll
        for (int f0 = 0; f0 < 256; f0 += 128) {
            int f = f0 + lane * 4;
            int base = n * 1024 + h * 256 + f;
            float4 xa = *(const float4*)&g_xpA[base];
            float4 xb = *(const float4*)&g_xpB[base];
            float4 x  = make_float4(xa.x + xb.x, xa.y + xb.y, xa.z + xb.z, xa.w + xb.w);
            float4 ws = *(const float4*)&g1as[h * 256 + f];
            float4 wd = *(const float4*)&g1ad[h * 256 + f];
            s  = fmaf(x.x, ws.x, fmaf(x.y, ws.y, fmaf(x.z, ws.z, fmaf(x.w, ws.w, s))));
            ds = fmaf(x.x, wd.x, fmaf(x.y, wd.y, fmaf(x.z, wd.z, fmaf(x.w, wd.w, ds))));
        }
        #pragma unroll
        for (int o = 16; o > 0; o >>= 1) {
            s  += __shfl_down_sync(0xffffffffu, s, o);
            ds += __shfl_down_sync(0xffffffffu, ds, o);
        }
        if (lane == 0) { g_asrc[n * 4 + h] = s; g_adst[n * 4 + h] = ds; }
    } else {
        int base = (blockIdx.x - 960) * 4096;
        #pragma unroll
        for (int j = 0; j < 4; j++) {
            int idx = base + (tid + j * 256) * 4;
            float4 a = *(const float4*)&g_xpA[idx];
            float4 b = *(const float4*)&g_xpB[idx];
            *(float4*)&g_xp[idx] = make_float4(a.x + b.x, a.y + b.y, a.z + b.z, a.w + b.w);
        }
    }
}

// ---------------- L3a: topk (96 blocks, warp per row) ----------------
__global__ __launch_bounds__(256) void topk_kernel(int* __restrict__ nbr,
                                                   const float* __restrict__ rel) {
    const int tid = threadIdx.x;
    const int warp = tid >> 5, lane = tid & 31;
    const int n = blockIdx.x * 8 + warp;
    const float* row = rel + n * NNODES;
    float v[24];
    #pragma unroll
    for (int m = 0; m < 24; m++) v[m] = row[m * 32 + lane];
    unsigned removed = 0;
    for (int s = 0; s < 20; s++) {
        float best = -3.4e38f; int bm = -1;
        #pragma unroll
        for (int m = 0; m < 24; m++) {
            bool alive = ((removed >> m) & 1u) == 0u;
            if (alive && v[m] > best) { best = v[m]; bm = m; }
        }
        int bidx = (bm >= 0) ? (bm * 32 + lane) : (1 << 20);
        #pragma unroll
        for (int o = 16; o > 0; o >>= 1) {
            float ov = __shfl_xor_sync(0xffffffffu, best, o);
            int   oi = __shfl_xor_sync(0xffffffffu, bidx, o);
            if (ov > best || (ov == best && oi < bidx)) { best = ov; bidx = oi; }
        }
        if (lane == (bidx & 31)) removed |= 1u << (bidx >> 5);
        if (lane == 0) nbr[n * KNB + s] = bidx;
    }
    if (lane == 0) nbr[n * KNB + 20] = n;
}

// ---------------- L3b: gat1 (768 blocks, one row per block) ----------------
__global__ __launch_bounds__(256) void gat1_kernel(const float* __restrict__ g1b) {
    __shared__ float alpha[KNB * 4];
    __shared__ int nb[KNB];
    const int n = blockIdx.x, tid = threadIdx.x;
    if (tid < KNB) nb[tid] = g_nbr[n * KNB + tid];
    __syncthreads();
    if (tid < 4) {
        int h = tid;
        float ad = g_adst[n * 4 + h];
        float lg[KNB]; float mx = -3.4e38f;
        #pragma unroll
        for (int k = 0; k < KNB; k++) {
            float v = g_asrc[nb[k] * 4 + h] + ad;
            v = (v > 0.f) ? v : 0.2f * v;
            lg[k] = v; mx = fmaxf(mx, v);
        }
        float ssum = 0.f;
        #pragma unroll
        for (int k = 0; k < KNB; k++) { lg[k] = __expf(lg[k] - mx); ssum += lg[k]; }
        float inv = 1.0f / ssum;
        #pragma unroll
        for (int k = 0; k < KNB; k++) alpha[k * 4 + h] = lg[k] * inv;
    }
    __syncthreads();
    const int c4 = tid * 4, h = c4 >> 8;
    float4 acc = make_float4(0.f, 0.f, 0.f, 0.f);
    #pragma unroll
    for (int k = 0; k < KNB; k++) {
        float a = alpha[k * 4 + h];
        float4 x = *(const float4*)&g_xp[nb[k] * 1024 + c4];
        acc.x = fmaf(a, x.x, acc.x); acc.y = fmaf(a, x.y, acc.y);
        acc.z = fmaf(a, x.z, acc.z); acc.w = fmaf(a, x.w, acc.w);
    }
    float4 b4 = *(const float4*)&g1b[c4];
    *(float4*)&g_h1[n * 1024 + c4] =
        make_float4(fmaxf(acc.x + b4.x, 0.f), fmaxf(acc.y + b4.y, 0.f),
                    fmaxf(acc.z + b4.z, 0.f), fmaxf(acc.w + b4.w, 0.f));
}

// ---------------- L4: thin GEMM splitK16 (96) + gat2 proj warp-per-row (96) ----------------
__global__ __launch_bounds__(256) void thin_gat2_kernel(const float* __restrict__ rW1,
                                                        const float* __restrict__ g2W,
                                                        const float* __restrict__ g2as,
                                                        const float* __restrict__ g2ad) {
    const int tid = threadIdx.x;
    if (blockIdx.x < 96) {
        int split = blockIdx.x / 6;      // 0..15
        int mt = blockIdx.x % 6;
        int row0 = mt * 128;
        gemm128<false>(g_h1 + row0 * 1024 + split * 64, 1024,
                       rW1 + split * 64 * 128, 128,
                       g_hidP + split * (NNODES * 128) + row0 * 128, 128,
                       0, 64, nullptr, nullptr, 0);
    } else {
        const int warp = tid >> 5, lane = tid & 31;
        const int n = (blockIdx.x - 96) * 8 + warp;
        float a0 = 0.f, a1 = 0.f;
        #pragma unroll
        for (int it = 0; it < 8; it++) {
            int f = it * 128 + lane * 4;
            float4 h = *(const float4*)&g_h1[n * 1024 + f];
            float4 w01 = *(const float4*)&g2W[f * 2];
            float4 w23 = *(const float4*)&g2W[f * 2 + 4];
            a0 = fmaf(h.x, w01.x, fmaf(h.y, w01.z, fmaf(h.z, w23.x, fmaf(h.w, w23.z, a0))));
            a1 = fmaf(h.x, w01.y, fmaf(h.y, w01.w, fmaf(h.z, w23.y, fmaf(h.w, w23.w, a1))));
        }
        #pragma unroll
        for (int o = 16; o > 0; o >>= 1) {
            a0 += __shfl_down_sync(0xffffffffu, a0, o);
            a1 += __shfl_down_sync(0xffffffffu, a1, o);
        }
        if (lane == 0) {
            g_x2[n * 2 + 0] = a0; g_x2[n * 2 + 1] = a1;
            g_a2s[n] = a0 * g2as[0] + a1 * g2as[1];
            g_a2d[n] = a0 * g2ad[0] + a1 * g2ad[1];
        }
    }
}

// ---------------- L5: final ----------------
__global__ void final_kernel(const float* __restrict__ g2b,
                             const float* __restrict__ rW1,
                             const float* __restrict__ rb1,
                             const float* __restrict__ rW2,
                             const float* __restrict__ rb2,
                             const float* __restrict__ boxes,
                             float* __restrict__ out) {
    __shared__ float hid_s[128];
    __shared__ float delta[4];
    const int n = blockIdx.x, tid = threadIdx.x;

    {
        float s = 0.f;
        #pragma unroll
        for (int p = 0; p < 16; p++) s += g_hidP[p * (NNODES * 128) + n * 128 + tid];
        const float inv800 = 1.0f / 800.0f;
        float4 bx4 = *(const float4*)(boxes + n * 4);
        s = fmaf(bx4.x * inv800, rW1[1024 * 128 + tid],
            fmaf(bx4.y * inv800, rW1[1025 * 128 + tid],
            fmaf(bx4.z * inv800, rW1[1026 * 128 + tid],
            fmaf(bx4.w * inv800, rW1[1027 * 128 + tid], s))));
        hid_s[tid] = fmaxf(s + rb1[tid], 0.f);
    }
    __syncthreads();

    const int c = tid >> 5, lane = tid & 31;
    float acc = 0.f;
    #pragma unroll
    for (int i0 = 0; i0 < 128; i0 += 32)
        acc = fmaf(hid_s[i0 + lane], rW2[(i0 + lane) * 4 + c], acc);
    #pragma unroll
    for (int o = 16; o > 0; o >>= 1) acc += __shfl_down_sync(0xffffffffu, acc, o);
    if (lane == 0) delta[c] = acc + rb2[c];
    __syncthreads();

    if (tid == 0) {
        float ad = g_a2d[n];
        float lg[KNB]; float mx = -3.4e38f;
        int nb[KNB];
        #pragma unroll
        for (int k = 0; k < KNB; k++) nb[k] = g_nbr[n * KNB + k];
        #pragma unroll
        for (int k = 0; k < KNB; k++) {
            float v = g_a2s[nb[k]] + ad;
            v = (v > 0.f) ? v : 0.2f * v;
            lg[k] = v; mx = fmaxf(mx, v);
        }
        float ssum = 0.f;
        #pragma unroll
        for (int k = 0; k < KNB; k++) { lg[k] = expf(lg[k] - mx); ssum += lg[k]; }
        float inv = 1.0f / ssum;
        float o0 = 0.f, o1 = 0.f;
        #pragma unroll
        for (int k = 0; k < KNB; k++) {
            float a = lg[k] * inv;
            o0 = fmaf(a, g_x2[nb[k] * 2 + 0], o0);
            o1 = fmaf(a, g_x2[nb[k] * 2 + 1], o1);
        }
        out[n * 6 + 0] = o0 + g2b[0];
        out[n * 6 + 1] = o1 + g2b[1];
        float x0 = boxes[n * 4 + 0], y0 = boxes[n * 4 + 1];
        float x1 = boxes[n * 4 + 2], y1 = boxes[n * 4 + 3];
        float pw = x1 - x0, ph = y1 - y0;
        float pcx = x0 + 0.5f * pw, pcy = y0 + 0.5f * ph;
        float gcx = delta[0] * pw + pcx, gcy = delta[1] * ph + pcy;
        float gw = expf(delta[2]) * pw, gh = expf(delta[3]) * ph;
        out[n * 6 + 2] = gcx - 0.5f * gw;
        out[n * 6 + 3] = gcy - 0.5f * gh;
        out[n * 6 + 4] = gcx + 0.5f * gw;
        out[n * 6 + 5] = gcy + 0.5f * gh;
    }
}

// ---------------- launch ----------------
extern "C" void kernel_launch(void* const* d_in, const int* in_sizes, int n_in,
                              void* d_out, int out_size) {
    const float* feats = (const float*)d_in[0];
    const float* boxes = (const float*)d_in[1];
    const float* W1    = (const float*)d_in[2];
    const float* b1    = (const float*)d_in[3];
    const float* W2    = (const float*)d_in[4];
    const float* b2    = (const float*)d_in[5];
    const float* g1W   = (const float*)d_in[6];
    const float* g1as  = (const float*)d_in[7];
    const float* g1ad  = (const float*)d_in[8];
    const float* g1b   = (const float*)d_in[9];
    const float* g2W   = (const float*)d_in[10];
    const float* g2as  = (const float*)d_in[11];
    const float* g2ad  = (const float*)d_in[12];
    const float* g2b   = (const float*)d_in[13];
    const float* rW1   = (const float*)d_in[14];
    const float* rb1   = (const float*)d_in[15];
    const float* rW2   = (const float*)d_in[16];
    const float* rb2   = (const float*)d_in[17];
    float* out = (float*)d_out;

    float* pRel;
    int* pNbr;
    cudaGetSymbolAddress((void**)&pRel, g_rel);
    cudaGetSymbolAddress((void**)&pNbr, g_nbr);

    gemm_main<<<144, 256>>>(feats, W1, g1W, boxes);
    rel_attn_kernel<<<576 + 384 + 192, 256>>>(boxes, W1, b1, W2, b2, g1as, g1ad, pRel);
    topk_kernel<<<96, 256>>>(pNbr, pRel);
    gat1_kernel<<<NNODES, 256>>>(g1b);
    thin_gat2_kernel<<<96 + 96, 256>>>(rW1, g2W, g2as, g2ad);
    final_kernel<<<NNODES, 128>>>(g2b, rW1, rb1, rW2, rb2, boxes, out);
}

// round 13
// speedup vs baseline: 1.0868x; 1.0868x over previous
#include <cuda_runtime.h>
#include <cstdint>
#include <math.h>

#define NNODES 768
#define KNB    21
typedef unsigned long long ull;

// ---------- f32x2 PTX helpers ----------
#define FMA2(d, a, b, c) \
    asm("fma.rn.f32x2 %0, %1, %2, %3;" : "=l"(d) : "l"(a), "l"(b), "l"(c))
#define ADD2(d, a, b) \
    asm("add.rn.f32x2 %0, %1, %2;" : "=l"(d) : "l"(a), "l"(b))
#define PACK_DUP(d, s) \
    asm("mov.b64 %0, {%1, %1};" : "=l"(d) : "f"(s))
#define UNPACK2(lo, hi, v) \
    asm("mov.b64 {%0, %1}, %2;" : "=f"(lo), "=f"(hi) : "l"(v))

// ---------------- scratch ----------------
__device__ float g_fafbA[NNODES * 512];
__device__ float g_fafbB[NNODES * 512];
__device__ float g_xpA[NNODES * 1024];
__device__ float g_xpB[NNODES * 1024];
__device__ float g_xp[NNODES * 1024];
__device__ float g_rel[NNODES * NNODES];
__device__ int   g_nbr[NNODES * KNB];
__device__ float g_asrc[NNODES * 4];
__device__ float g_adst[NNODES * 4];
__device__ float g_h1[NNODES * 1024];
__device__ float g_hidP[8 * NNODES * 128];
__device__ float g_x2[NNODES * 2];
__device__ float g_a2s[NNODES];
__device__ float g_a2d[NNODES];

// =========== shared 128x128 FFMA2 GEMM core (reg-prefetch double buffer) ===========
template<bool GEOM_TAIL>
__device__ __forceinline__ void gemm128(const float* __restrict__ Abase, int lda,
                                        const float* __restrict__ Bbase, int ldb,
                                        float* __restrict__ Cbase, int ldc,
                                        int k0, int k1,
                                        const float* __restrict__ Wtail,
                                        const float* __restrict__ boxes, int row0) {
    __shared__ float As[16][132];
    __shared__ float Bs[16][132];
    __shared__ float Wt[4][128];

    const int tid = threadIdx.x;
    if (GEOM_TAIL && tid < 128) {
        int d = tid >> 5, c4 = (tid & 31) * 4;
        *(float4*)&Wt[d][c4] = *(const float4*)(Wtail + d * ldb + c4);
    }

    const int arow = tid >> 1, ak8 = (tid & 1) * 8;
    const int brow = tid >> 4, bc8 = (tid & 15) * 8;
    const int ty = tid >> 4, tx = tid & 15;

    ull acc[8][4];
    #pragma unroll
    for (int i = 0; i < 8; i++)
        #pragma unroll
        for (int j = 0; j < 4; j++) acc[i][j] = 0ull;

    float4 a0 = *(const float4*)(Abase + arow * lda + k0 + ak8);
    float4 a1 = *(const float4*)(Abase + arow * lda + k0 + ak8 + 4);
    float4 b0 = *(const float4*)(Bbase + (k0 + brow) * ldb + bc8);
    float4 b1 = *(const float4*)(Bbase + (k0 + brow) * ldb + bc8 + 4);

    for (int k = k0; k < k1; k += 16) {
        __syncthreads();
        As[ak8 + 0][arow] = a0.x; As[ak8 + 1][arow] = a0.y;
        As[ak8 + 2][arow] = a0.z; As[ak8 + 3][arow] = a0.w;
        As[ak8 + 4][arow] = a1.x; As[ak8 + 5][arow] = a1.y;
        As[ak8 + 6][arow] = a1.z; As[ak8 + 7][arow] = a1.w;
        *(float4*)&Bs[brow][bc8]     = b0;
        *(float4*)&Bs[brow][bc8 + 4] = b1;
        __syncthreads();
        if (k + 16 < k1) {
            a0 = *(const float4*)(Abase + arow * lda + k + 16 + ak8);
            a1 = *(const float4*)(Abase + arow * lda + k + 16 + ak8 + 4);
            b0 = *(const float4*)(Bbase + (k + 16 + brow) * ldb + bc8);
            b1 = *(const float4*)(Bbase + (k + 16 + brow) * ldb + bc8 + 4);
        }
        #pragma unroll
        for (int kk = 0; kk < 16; kk++) {
            float4 af0 = *(const float4*)&As[kk][ty * 8];
            float4 af1 = *(const float4*)&As[kk][ty * 8 + 4];
            float4 bf0 = *(const float4*)&Bs[kk][tx * 8];
            float4 bf1 = *(const float4*)&Bs[kk][tx * 8 + 4];
            ull a2[8], b2[4];
            PACK_DUP(a2[0], af0.x); PACK_DUP(a2[1], af0.y);
            PACK_DUP(a2[2], af0.z); PACK_DUP(a2[3], af0.w);
            PACK_DUP(a2[4], af1.x); PACK_DUP(a2[5], af1.y);
            PACK_DUP(a2[6], af1.z); PACK_DUP(a2[7], af1.w);
            b2[0] = ((const ull*)&bf0)[0]; b2[1] = ((const ull*)&bf0)[1];
            b2[2] = ((const ull*)&bf1)[0]; b2[3] = ((const ull*)&bf1)[1];
            #pragma unroll
            for (int i = 0; i < 8; i++) {
                FMA2(acc[i][0], a2[i], b2[0], acc[i][0]);
                FMA2(acc[i][1], a2[i], b2[1], acc[i][1]);
                FMA2(acc[i][2], a2[i], b2[2], acc[i][2]);
                FMA2(acc[i][3], a2[i], b2[3], acc[i][3]);
            }
        }
    }

    if (GEOM_TAIL) {
        __syncthreads();
        const float inv800 = 1.0f / 800.0f;
        #pragma unroll
        for (int i = 0; i < 8; i++) {
            int row = row0 + ty * 8 + i;
            float4 bx4 = *(const float4*)(boxes + row * 4);
            ull g2[4];
            PACK_DUP(g2[0], bx4.x * inv800); PACK_DUP(g2[1], bx4.y * inv800);
            PACK_DUP(g2[2], bx4.z * inv800); PACK_DUP(g2[3], bx4.w * inv800);
            #pragma unroll
            for (int d = 0; d < 4; d++) {
                const ull* wrow = (const ull*)&Wt[d][tx * 8];
                FMA2(acc[i][0], g2[d], wrow[0], acc[i][0]);
                FMA2(acc[i][1], g2[d], wrow[1], acc[i][1]);
                FMA2(acc[i][2], g2[d], wrow[2], acc[i][2]);
                FMA2(acc[i][3], g2[d], wrow[3], acc[i][3]);
            }
        }
    }

    #pragma unroll
    for (int i = 0; i < 8; i++) {
        float* crow = Cbase + (ty * 8 + i) * ldc + tx * 8;
        ulonglong2 o0; o0.x = acc[i][0]; o0.y = acc[i][1];
        ulonglong2 o1; o1.x = acc[i][2]; o1.y = acc[i][3];
        *(ulonglong2*)(crow)     = o0;
        *(ulonglong2*)(crow + 4) = o1;
    }
}

// =========== L1: fafb (48 blocks) + xp (96 blocks) ===========
__global__ __launch_bounds__(256) void gemm_main(const float* __restrict__ feats,
                                                 const float* __restrict__ W1,
                                                 const float* __restrict__ g1W,
                                                 const float* __restrict__ boxes) {
    const int blk = blockIdx.x;
    if (blk < 48) {
        int half = blk >= 24;
        int t = blk - half * 24;
        int bx = t & 3, by = t >> 2;
        int row0 = by * 128, col0 = bx * 128;
        const float* Bb = (col0 >= 256) ? (W1 + 1024 * 256 + (col0 - 256)) : (W1 + col0);
        gemm128<false>(feats + row0 * 1024, 1024, Bb, 256,
                       (half ? g_fafbB : g_fafbA) + row0 * 512 + col0, 512,
                       half * 512, half * 512 + 512, nullptr, nullptr, 0);
    } else {
        int t = blk - 48;
        int half = t >= 48;
        int tt = t - half * 48;
        int bx = tt & 7, by = tt >> 3;
        int row0 = by * 128, col0 = bx * 128;
        if (half)
            gemm128<true>(feats + row0 * 1024, 1024, g1W + col0, 1024,
                          g_xpB + row0 * 1024 + col0, 1024,
                          512, 1024, g1W + 1024 * 1024 + col0, boxes, row0);
        else
            gemm128<false>(feats + row0 * 1024, 1024, g1W + col0, 1024,
                           g_xpA + row0 * 1024 + col0, 1024,
                           0, 512, nullptr, nullptr, 0);
    }
}

// ---------------- rel body ----------------
__device__ __forceinline__ void rel_body(int blk,
                                         const float* __restrict__ boxes,
                                         const float* __restrict__ W1,
                                         const float* __restrict__ b1,
                                         const float* __restrict__ W2,
                                         const float* __restrict__ b2,
                                         float* __restrict__ rel) {
    __shared__ float  fa_s[32][128];
    __shared__ float  fb_s[32 * 130];
    __shared__ float2 wg2_s[4][64];
    __shared__ float  w2_s[128];
    __shared__ float  bb_s[256];

    const int i0 = (blk / 24) * 32, j0 = (blk % 24) * 32;
    const int tid = threadIdx.x;
    const int tx = tid & 31, ty = tid >> 5;

    if (tid < 128) { bb_s[tid] = boxes[i0 * 4 + tid]; bb_s[128 + tid] = boxes[j0 * 4 + tid]; }
    __syncthreads();

    float bj0 = bb_s[128 + tx * 4 + 0], bj1 = bb_s[128 + tx * 4 + 1];
    float bj2 = bb_s[128 + tx * 4 + 2], bj3 = bb_s[128 + tx * 4 + 3];
    ull d2[4][4];
    #pragma unroll
    for (int r = 0; r < 4; r++) {
        int ii = ty * 4 + r;
        float d0 = fabsf(bb_s[ii * 4 + 0] - bj0);
        float d1 = fabsf(bb_s[ii * 4 + 1] - bj1);
        float d3 = fabsf(bb_s[ii * 4 + 2] - bj2);
        float d4 = fabsf(bb_s[ii * 4 + 3] - bj3);
        PACK_DUP(d2[r][0], d0); PACK_DUP(d2[r][1], d1);
        PACK_DUP(d2[r][2], d3); PACK_DUP(d2[r][3], d4);
    }

    float acc[4] = {0.f, 0.f, 0.f, 0.f};
    for (int c0 = 0; c0 < 256; c0 += 128) {
        __syncthreads();
        for (int t = tid; t < 1024; t += 256) {
            int r = t >> 5, h4 = (t & 31) * 4;
            float4 vA = *(const float4*)&g_fafbA[(i0 + r) * 512 + c0 + h4];
            float4 vB = *(const float4*)&g_fafbB[(i0 + r) * 512 + c0 + h4];
            float4 bb = *(const float4*)&b1[c0 + h4];
            *(float4*)&fa_s[r][h4] = make_float4(vA.x + vB.x + bb.x, vA.y + vB.y + bb.y,
                                                 vA.z + vB.z + bb.z, vA.w + vB.w + bb.w);
            float4 wA = *(const float4*)&g_fafbA[(j0 + r) * 512 + 256 + c0 + h4];
            float4 wB = *(const float4*)&g_fafbB[(j0 + r) * 512 + 256 + c0 + h4];
            *(float2*)&fb_s[r * 130 + h4]     = make_float2(wA.x + wB.x, wA.y + wB.y);
            *(float2*)&fb_s[r * 130 + h4 + 2] = make_float2(wA.z + wB.z, wA.w + wB.w);
        }
        {
            int comp = tid >> 6, m = tid & 63;
            const float* wrow = W1 + (2048 + comp) * 256 + c0;
            wg2_s[comp][m] = make_float2(wrow[2 * m], wrow[2 * m + 1]);
        }
        if (tid < 128) w2_s[tid] = W2[c0 + tid];
        __syncthreads();
        #pragma unroll 2
        for (int m = 0; m < 64; m++) {
            ull fb2 = *(const ull*)&fb_s[tx * 130 + 2 * m];
            ull wgx = *(const ull*)&wg2_s[0][m];
            ull wgy = *(const ull*)&wg2_s[1][m];
            ull wgz = *(const ull*)&wg2_s[2][m];
            ull wgw = *(const ull*)&wg2_s[3][m];
            float w2a = w2_s[2 * m], w2b = w2_s[2 * m + 1];
            #pragma unroll
            for (int r = 0; r < 4; r++) {
                ull fa2 = *(const ull*)&fa_s[ty * 4 + r][2 * m];
                ull s;
                ADD2(s, fa2, fb2);
                FMA2(s, d2[r][0], wgx, s);
                FMA2(s, d2[r][1], wgy, s);
                FMA2(s, d2[r][2], wgz, s);
                FMA2(s, d2[r][3], wgw, s);
                float lo, hi;
                UNPACK2(lo, hi, s);
                lo = fmaxf(lo, 0.f); hi = fmaxf(hi, 0.f);
                acc[r] = fmaf(lo, w2a, acc[r]);
                acc[r] = fmaf(hi, w2b, acc[r]);
            }
        }
    }
    float b2v = b2[0];
    #pragma unroll
    for (int r = 0; r < 4; r++) {
        int i = i0 + ty * 4 + r, j = j0 + tx;
        float v = acc[r] + b2v;
        if (i == j) v = -1e9f;
        rel[i * NNODES + j] = v;
    }
}

// ---------------- L2: rel (576) + attn coef w/ xp write-through (384) ----------------
__global__ __launch_bounds__(256) void rel_attn_kernel(const float* __restrict__ boxes,
                                                       const float* __restrict__ W1,
                                                       const float* __restrict__ b1,
                                                       const float* __restrict__ W2,
                                                       const float* __restrict__ b2,
                                                       const float* __restrict__ g1as,
                                                       const float* __restrict__ g1ad,
                                                       float* __restrict__ rel) {
    const int tid = threadIdx.x;
    if (blockIdx.x < 576) {
        rel_body(blockIdx.x, boxes, W1, b1, W2, b2, rel);
    } else {
        // attn coef + write-through of g_xp = g_xpA + g_xpB.
        // 384 blocks x 2 nodes: every element of xp touched exactly once.
        const int n = (blockIdx.x - 576) * 2 + (tid >> 7);
        const int wtid = tid & 127;
        const int h = wtid >> 5, lane = tid & 31;
        float s = 0.f, ds = 0.f;
        #pragma unroll
        for (int f0 = 0; f0 < 256; f0 += 128) {
            int f = f0 + lane * 4;
            int base = n * 1024 + h * 256 + f;
            float4 xa = *(const float4*)&g_xpA[base];
            float4 xb = *(const float4*)&g_xpB[base];
            float4 x  = make_float4(xa.x + xb.x, xa.y + xb.y, xa.z + xb.z, xa.w + xb.w);
            *(float4*)&g_xp[base] = x;
            float4 ws = *(const float4*)&g1as[h * 256 + f];
            float4 wd = *(const float4*)&g1ad[h * 256 + f];
            s  = fmaf(x.x, ws.x, fmaf(x.y, ws.y, fmaf(x.z, ws.z, fmaf(x.w, ws.w, s))));
            ds = fmaf(x.x, wd.x, fmaf(x.y, wd.y, fmaf(x.z, wd.z, fmaf(x.w, wd.w, ds))));
        }
        #pragma unroll
        for (int o = 16; o > 0; o >>= 1) {
            s  += __shfl_down_sync(0xffffffffu, s, o);
            ds += __shfl_down_sync(0xffffffffu, ds, o);
        }
        if (lane == 0) { g_asrc[n * 4 + h] = s; g_adst[n * 4 + h] = ds; }
    }
}

// ---------------- L3a: topk (96 blocks, warp per row) ----------------
__global__ __launch_bounds__(256) void topk_kernel(int* __restrict__ nbr,
                                                   const float* __restrict__ rel) {
    const int tid = threadIdx.x;
    const int warp = tid >> 5, lane = tid & 31;
    const int n = blockIdx.x * 8 + warp;
    const float* row = rel + n * NNODES;
    float v[24];
    #pragma unroll
    for (int m = 0; m < 24; m++) v[m] = row[m * 32 + lane];
    unsigned removed = 0;
    for (int s = 0; s < 20; s++) {
        float best = -3.4e38f; int bm = -1;
        #pragma unroll
        for (int m = 0; m < 24; m++) {
            bool alive = ((removed >> m) & 1u) == 0u;
            if (alive && v[m] > best) { best = v[m]; bm = m; }
        }
        int bidx = (bm >= 0) ? (bm * 32 + lane) : (1 << 20);
        #pragma unroll
        for (int o = 16; o > 0; o >>= 1) {
            float ov = __shfl_xor_sync(0xffffffffu, best, o);
            int   oi = __shfl_xor_sync(0xffffffffu, bidx, o);
            if (ov > best || (ov == best && oi < bidx)) { best = ov; bidx = oi; }
        }
        if (lane == (bidx & 31)) removed |= 1u << (bidx >> 5);
        if (lane == 0) nbr[n * KNB + s] = bidx;
    }
    if (lane == 0) nbr[n * KNB + 20] = n;
}

// ---------------- L3b: gat1 (768 blocks, one row per block) ----------------
__global__ __launch_bounds__(256) void gat1_kernel(const float* __restrict__ g1b) {
    __shared__ float alpha[KNB * 4];
    __shared__ int nb[KNB];
    const int n = blockIdx.x, tid = threadIdx.x;
    if (tid < KNB) nb[tid] = g_nbr[n * KNB + tid];
    __syncthreads();
    if (tid < 4) {
        int h = tid;
        float ad = g_adst[n * 4 + h];
        float lg[KNB]; float mx = -3.4e38f;
        #pragma unroll
        for (int k = 0; k < KNB; k++) {
            float v = g_asrc[nb[k] * 4 + h] + ad;
            v = (v > 0.f) ? v : 0.2f * v;
            lg[k] = v; mx = fmaxf(mx, v);
        }
        float ssum = 0.f;
        #pragma unroll
        for (int k = 0; k < KNB; k++) { lg[k] = __expf(lg[k] - mx); ssum += lg[k]; }
        float inv = 1.0f / ssum;
        #pragma unroll
        for (int k = 0; k < KNB; k++) alpha[k * 4 + h] = lg[k] * inv;
    }
    __syncthreads();
    const int c4 = tid * 4, h = c4 >> 8;
    float4 acc = make_float4(0.f, 0.f, 0.f, 0.f);
    #pragma unroll
    for (int k = 0; k < KNB; k++) {
        float a = alpha[k * 4 + h];
        float4 x = *(const float4*)&g_xp[nb[k] * 1024 + c4];
        acc.x = fmaf(a, x.x, acc.x); acc.y = fmaf(a, x.y, acc.y);
        acc.z = fmaf(a, x.z, acc.z); acc.w = fmaf(a, x.w, acc.w);
    }
    float4 b4 = *(const float4*)&g1b[c4];
    *(float4*)&g_h1[n * 1024 + c4] =
        make_float4(fmaxf(acc.x + b4.x, 0.f), fmaxf(acc.y + b4.y, 0.f),
                    fmaxf(acc.z + b4.z, 0.f), fmaxf(acc.w + b4.w, 0.f));
}

// ---------------- L4: thin GEMM splitK8 (48) + gat2 proj warp-per-row (96) ----------------
__global__ __launch_bounds__(256) void thin_gat2_kernel(const float* __restrict__ rW1,
                                                        const float* __restrict__ g2W,
                                                        const float* __restrict__ g2as,
                                                        const float* __restrict__ g2ad) {
    const int tid = threadIdx.x;
    if (blockIdx.x < 48) {
        int split = blockIdx.x / 6;
        int mt = blockIdx.x % 6;
        int row0 = mt * 128;
        gemm128<false>(g_h1 + row0 * 1024 + split * 128, 1024,
                       rW1 + split * 128 * 128, 128,
                       g_hidP + split * (NNODES * 128) + row0 * 128, 128,
                       0, 128, nullptr, nullptr, 0);
    } else {
        const int warp = tid >> 5, lane = tid & 31;
        const int n = (blockIdx.x - 48) * 8 + warp;
        float a0 = 0.f, a1 = 0.f;
        #pragma unroll
        for (int it = 0; it < 8; it++) {
            int f = it * 128 + lane * 4;
            float4 h = *(const float4*)&g_h1[n * 1024 + f];
            float4 w01 = *(const float4*)&g2W[f * 2];
            float4 w23 = *(const float4*)&g2W[f * 2 + 4];
            a0 = fmaf(h.x, w01.x, fmaf(h.y, w01.z, fmaf(h.z, w23.x, fmaf(h.w, w23.z, a0))));
            a1 = fmaf(h.x, w01.y, fmaf(h.y, w01.w, fmaf(h.z, w23.y, fmaf(h.w, w23.w, a1))));
        }
        #pragma unroll
        for (int o = 16; o > 0; o >>= 1) {
            a0 += __shfl_down_sync(0xffffffffu, a0, o);
            a1 += __shfl_down_sync(0xffffffffu, a1, o);
        }
        if (lane == 0) {
            g_x2[n * 2 + 0] = a0; g_x2[n * 2 + 1] = a1;
            g_a2s[n] = a0 * g2as[0] + a1 * g2as[1];
            g_a2d[n] = a0 * g2ad[0] + a1 * g2ad[1];
        }
    }
}

// ---------------- L5: final ----------------
__global__ void final_kernel(const float* __restrict__ g2b,
                             const float* __restrict__ rW1,
                             const float* __restrict__ rb1,
                             const float* __restrict__ rW2,
                             const float* __restrict__ rb2,
                             const float* __restrict__ boxes,
                             float* __restrict__ out) {
    __shared__ float hid_s[128];
    __shared__ float delta[4];
    const int n = blockIdx.x, tid = threadIdx.x;

    {
        float s = 0.f;
        #pragma unroll
        for (int p = 0; p < 8; p++) s += g_hidP[p * (NNODES * 128) + n * 128 + tid];
        const float inv800 = 1.0f / 800.0f;
        float4 bx4 = *(const float4*)(boxes + n * 4);
        s = fmaf(bx4.x * inv800, rW1[1024 * 128 + tid],
            fmaf(bx4.y * inv800, rW1[1025 * 128 + tid],
            fmaf(bx4.z * inv800, rW1[1026 * 128 + tid],
            fmaf(bx4.w * inv800, rW1[1027 * 128 + tid], s))));
        hid_s[tid] = fmaxf(s + rb1[tid], 0.f);
    }
    __syncthreads();

    const int c = tid >> 5, lane = tid & 31;
    float acc = 0.f;
    #pragma unroll
    for (int i0 = 0; i0 < 128; i0 += 32)
        acc = fmaf(hid_s[i0 + lane], rW2[(i0 + lane) * 4 + c], acc);
    #pragma unroll
    for (int o = 16; o > 0; o >>= 1) acc += __shfl_down_sync(0xffffffffu, acc, o);
    if (lane == 0) delta[c] = acc + rb2[c];
    __syncthreads();

    if (tid == 0) {
        float ad = g_a2d[n];
        float lg[KNB]; float mx = -3.4e38f;
        int nb[KNB];
        #pragma unroll
        for (int k = 0; k < KNB; k++) nb[k] = g_nbr[n * KNB + k];
        #pragma unroll
        for (int k = 0; k < KNB; k++) {
            float v = g_a2s[nb[k]] + ad;
            v = (v > 0.f) ? v : 0.2f * v;
            lg[k] = v; mx = fmaxf(mx, v);
        }
        float ssum = 0.f;
        #pragma unroll
        for (int k = 0; k < KNB; k++) { lg[k] = expf(lg[k] - mx); ssum += lg[k]; }
        float inv = 1.0f / ssum;
        float o0 = 0.f, o1 = 0.f;
        #pragma unroll
        for (int k = 0; k < KNB; k++) {
            float a = lg[k] * inv;
            o0 = fmaf(a, g_x2[nb[k] * 2 + 0], o0);
            o1 = fmaf(a, g_x2[nb[k] * 2 + 1], o1);
        }
        out[n * 6 + 0] = o0 + g2b[0];
        out[n * 6 + 1] = o1 + g2b[1];
        float x0 = boxes[n * 4 + 0], y0 = boxes[n * 4 + 1];
        float x1 = boxes[n * 4 + 2], y1 = boxes[n * 4 + 3];
        float pw = x1 - x0, ph = y1 - y0;
        float pcx = x0 + 0.5f * pw, pcy = y0 + 0.5f * ph;
        float gcx = delta[0] * pw + pcx, gcy = delta[1] * ph + pcy;
        float gw = expf(delta[2]) * pw, gh = expf(delta[3]) * ph;
        out[n * 6 + 2] = gcx - 0.5f * gw;
        out[n * 6 + 3] = gcy - 0.5f * gh;
        out[n * 6 + 4] = gcx + 0.5f * gw;
        out[n * 6 + 5] = gcy + 0.5f * gh;
    }
}

// ---------------- launch ----------------
extern "C" void kernel_launch(void* const* d_in, const int* in_sizes, int n_in,
                              void* d_out, int out_size) {
    const float* feats = (const float*)d_in[0];
    const float* boxes = (const float*)d_in[1];
    const float* W1    = (const float*)d_in[2];
    const float* b1    = (const float*)d_in[3];
    const float* W2    = (const float*)d_in[4];
    const float* b2    = (const float*)d_in[5];
    const float* g1W   = (const float*)d_in[6];
    const float* g1as  = (const float*)d_in[7];
    const float* g1ad  = (const float*)d_in[8];
    const float* g1b   = (const float*)d_in[9];
    const float* g2W   = (const float*)d_in[10];
    const float* g2as  = (const float*)d_in[11];
    const float* g2ad  = (const float*)d_in[12];
    const float* g2b   = (const float*)d_in[13];
    const float* rW1   = (const float*)d_in[14];
    const float* rb1   = (const float*)d_in[15];
    const float* rW2   = (const float*)d_in[16];
    const float* rb2   = (const float*)d_in[17];
    float* out = (float*)d_out;

    float* pRel;
    int* pNbr;
    cudaGetSymbolAddress((void**)&pRel, g_rel);
    cudaGetSymbolAddress((void**)&pNbr, g_nbr);

    gemm_main<<<144, 256>>>(feats, W1, g1W, boxes);
    rel_attn_kernel<<<576 + 384, 256>>>(boxes, W1, b1, W2, b2, g1as, g1ad, pRel);
    topk_kernel<<<96, 256>>>(pNbr, pRel);
    gat1_kernel<<<NNODES, 256>>>(g1b);
    thin_gat2_kernel<<<48 + 96, 256>>>(rW1, g2W, g2as, g2ad);
    final_kernel<<<NNODES, 128>>>(g2b, rW1, rb1, rW2, rb2, boxes, out);
}